// round 1
// baseline (speedup 1.0000x reference)
#include <cuda_runtime.h>
#include <math.h>

// ---------------------------------------------------------------------------
// Problem constants
// ---------------------------------------------------------------------------
#define BATCH 8
#define LTOK  4800
#define CDIM  256
#define HEADS 8
#define DHEAD 32
#define NPROT 8
#define NLAYER 4
#define NTOK  (BATCH * LTOK)          // 38400
#define EPS_ATTN 1e-6f
#define EPS_LN   1e-5f

// Output layout (floats), tuple order:
// feat0, feat1, class0, class1, f0p, f1p, prototype
#define OF_F0    0
#define OF_F1    (NTOK * CDIM)                       // 9830400
#define OF_C0    (2 * NTOK * CDIM)                   // 19660800
#define OF_C1    (OF_C0 + NTOK)
#define OF_F0P   (OF_C1 + NTOK)
#define OF_F1P   (OF_F0P + NTOK * NPROT)
#define OF_PROT  (OF_F1P + NTOK * NPROT)

// ---------------------------------------------------------------------------
// Device scratch (no allocation allowed)
// ---------------------------------------------------------------------------
__device__ float g_q  [NTOK * CDIM];
__device__ float g_k  [NTOK * CDIM];
__device__ float g_v  [NTOK * CDIM];
__device__ float g_msg[NTOK * CDIM];
__device__ float g_hid[NTOK * 2 * CDIM];
__device__ float g_kv [BATCH * NPROT * HEADS * DHEAD * DHEAD];  // [b][c][h][d][e]
__device__ float g_ks [BATCH * NPROT * HEADS * DHEAD];          // [b][c][h][d]
__device__ int   g_cls0[NTOK];
__device__ int   g_cls1[NTOK];

// ---------------------------------------------------------------------------
// Helpers
// ---------------------------------------------------------------------------
__device__ __forceinline__ float warp_sum(float v) {
    #pragma unroll
    for (int o = 16; o; o >>= 1) v += __shfl_xor_sync(0xffffffffu, v, o);
    return v;
}

// ---------------------------------------------------------------------------
// Tiled SGEMM: C[M,N] = f(A[M,K] @ W[K,N]); A row stride = lda.
// CONCAT: A covers k<256 (lda=256), A2 covers k>=256 (lda=256), K=512.
// EPI: 0 none, 1 phi=elu+1, 2 relu
// ---------------------------------------------------------------------------
#define BM 128
#define BN 128
#define BK 16

template <int EPI, bool CONCAT>
__global__ __launch_bounds__(256)
void gemm_kernel(const float* __restrict__ A, const float* __restrict__ A2, int lda,
                 const float* __restrict__ W, int N, int K,
                 float* __restrict__ C)
{
    __shared__ float As[BK][BM + 4];
    __shared__ float Bs[BK][BN];

    const int tid = threadIdx.x;
    const int m0 = blockIdx.y * BM;
    const int n0 = blockIdx.x * BN;
    const int tx = tid & 15;
    const int ty = tid >> 4;

    float acc[8][8];
    #pragma unroll
    for (int i = 0; i < 8; i++)
        #pragma unroll
        for (int j = 0; j < 8; j++) acc[i][j] = 0.f;

    for (int k0 = 0; k0 < K; k0 += BK) {
        const float* Asrc = A;
        int kofs = k0;
        if (CONCAT && k0 >= 256) { Asrc = A2; kofs = k0 - 256; }

        // Load A tile (128 rows x 16 k), transpose into As[k][m]
        #pragma unroll
        for (int i = 0; i < 2; i++) {
            int idx = tid + i * 256;          // 512 float4 slots
            int row = idx >> 2;               // 0..127
            int kq  = (idx & 3) * 4;          // 0,4,8,12
            float4 av = *(const float4*)(Asrc + (size_t)(m0 + row) * lda + kofs + kq);
            As[kq + 0][row] = av.x;
            As[kq + 1][row] = av.y;
            As[kq + 2][row] = av.z;
            As[kq + 3][row] = av.w;
        }
        // Load B tile (16 k x 128 n)
        #pragma unroll
        for (int i = 0; i < 2; i++) {
            int idx = tid + i * 256;
            int kr = idx >> 5;                // 0..15
            int nq = (idx & 31) * 4;          // 0..124
            *(float4*)&Bs[kr][nq] = *(const float4*)(W + (size_t)(k0 + kr) * N + n0 + nq);
        }
        __syncthreads();

        #pragma unroll
        for (int kk = 0; kk < BK; kk++) {
            float a[8], b[8];
            #pragma unroll
            for (int i = 0; i < 8; i++) a[i] = As[kk][ty * 8 + i];
            #pragma unroll
            for (int j = 0; j < 8; j++) b[j] = Bs[kk][tx * 8 + j];
            #pragma unroll
            for (int i = 0; i < 8; i++)
                #pragma unroll
                for (int j = 0; j < 8; j++) acc[i][j] += a[i] * b[j];
        }
        __syncthreads();
    }

    #pragma unroll
    for (int i = 0; i < 8; i++) {
        size_t row = (size_t)(m0 + ty * 8 + i);
        float* crow = C + row * N + n0 + tx * 8;
        #pragma unroll
        for (int j4 = 0; j4 < 2; j4++) {
            float4 o;
            float vals[4];
            #pragma unroll
            for (int t = 0; t < 4; t++) {
                float v = acc[i][j4 * 4 + t];
                if (EPI == 1) v = (v > 0.f) ? (v + 1.f) : expf(v);   // elu(v)+1
                else if (EPI == 2) v = fmaxf(v, 0.f);
                vals[t] = v;
            }
            o.x = vals[0]; o.y = vals[1]; o.z = vals[2]; o.w = vals[3];
            *(float4*)(crow + j4 * 4) = o;
        }
    }
}

// ---------------------------------------------------------------------------
// Classification: f p = feat_wo_pe @ proto^T, argmax -> class
// warp per token
// ---------------------------------------------------------------------------
__global__ __launch_bounds__(256)
void classify_kernel(const float* __restrict__ fwp, const float* __restrict__ proto,
                     float* __restrict__ out_fp, float* __restrict__ out_clsf,
                     int* __restrict__ cls)
{
    __shared__ float sp[NPROT][CDIM];
    int tid = threadIdx.x;
    #pragma unroll
    for (int i = 0; i < 8; i++) {
        int idx = tid + i * 256;
        sp[idx >> 8][idx & 255] = proto[idx];
    }
    __syncthreads();

    int tok = blockIdx.x * 8 + (tid >> 5);
    int lane = tid & 31;
    const float* f = fwp + (size_t)tok * CDIM;

    float acc[NPROT];
    #pragma unroll
    for (int p = 0; p < NPROT; p++) acc[p] = 0.f;

    #pragma unroll
    for (int i = 0; i < 8; i++) {
        float x = f[lane + i * 32];
        #pragma unroll
        for (int p = 0; p < NPROT; p++) acc[p] += x * sp[p][lane + i * 32];
    }
    #pragma unroll
    for (int p = 0; p < NPROT; p++) acc[p] = warp_sum(acc[p]);

    if (lane < NPROT) out_fp[(size_t)tok * NPROT + lane] = acc[lane];
    if (lane == 0) {
        int best = 0; float bv = acc[0];
        #pragma unroll
        for (int p = 1; p < NPROT; p++) if (acc[p] > bv) { bv = acc[p]; best = p; }
        cls[tok] = best;
        out_clsf[tok] = (float)best;
    }
}

// ---------------------------------------------------------------------------
// Per-class linear-attention stats:
//   kv[b,c,h,d,e] = sum_s w * phi_k[s,h,d] * v[s,h,e]
//   ks[b,c,h,d]   = sum_s w * phi_k[s,h,d],  w = (class==c && mask)
// One block per (b,c,h). Deterministic (no atomics).
// ---------------------------------------------------------------------------
__global__ __launch_bounds__(256)
void stats_kernel(const float* __restrict__ K_, const float* __restrict__ V_,
                  const int* __restrict__ cls, const int* __restrict__ mask,
                  float* __restrict__ KV, float* __restrict__ KS)
{
    __shared__ float sk[32][33];
    __shared__ float sv[32][33];

    int bid = blockIdx.x;        // b*64 + c*8 + h
    int h = bid & 7;
    int c = (bid >> 3) & 7;
    int b = bid >> 6;

    int tid = threadIdx.x;
    int d  = tid >> 3;           // 0..31
    int e0 = (tid & 7) * 4;      // 0,4,...,28

    float a0 = 0.f, a1 = 0.f, a2 = 0.f, a3 = 0.f;
    float ssum = 0.f;            // lanes tid<32 accumulate ks[tid]

    const float* Kb = K_ + (size_t)b * LTOK * CDIM + h * DHEAD;
    const float* Vb = V_ + (size_t)b * LTOK * CDIM + h * DHEAD;
    const int* clsb = cls + b * LTOK;
    const int* mb   = mask + b * LTOK;

    for (int s0 = 0; s0 < LTOK; s0 += 32) {
        #pragma unroll
        for (int i = 0; i < 4; i++) {
            int idx = tid + i * 256;       // 0..1023
            int s = idx >> 5;
            int dd = idx & 31;
            int t = s0 + s;
            float w = (clsb[t] == c && mb[t] != 0) ? 1.f : 0.f;
            sk[s][dd] = w * Kb[(size_t)t * CDIM + dd];
            sv[s][dd] = Vb[(size_t)t * CDIM + dd];
        }
        __syncthreads();
        #pragma unroll
        for (int s = 0; s < 32; s++) {
            float kd = sk[s][d];
            a0 += kd * sv[s][e0 + 0];
            a1 += kd * sv[s][e0 + 1];
            a2 += kd * sv[s][e0 + 2];
            a3 += kd * sv[s][e0 + 3];
        }
        if (tid < 32) {
            #pragma unroll
            for (int s = 0; s < 32; s++) ssum += sk[s][tid];
        }
        __syncthreads();
    }

    size_t o = ((((size_t)b * NPROT + c) * HEADS + h) * DHEAD + d) * DHEAD + e0;
    KV[o + 0] = a0; KV[o + 1] = a1; KV[o + 2] = a2; KV[o + 3] = a3;
    if (tid < 32) KS[(((size_t)b * NPROT + c) * HEADS + h) * DHEAD + tid] = ssum;
}

// ---------------------------------------------------------------------------
// Apply: msg[l,h,e] = (phi_q[l,h,:] @ kv[b,cls(l),h,:,e]) / (phi_q . ks + eps)
// warp per token
// ---------------------------------------------------------------------------
__global__ __launch_bounds__(256)
void apply_kernel(const float* __restrict__ Q, const float* __restrict__ KV,
                  const float* __restrict__ KS, const int* __restrict__ cls,
                  const int* __restrict__ mask, float* __restrict__ MSG)
{
    int tok = blockIdx.x * 8 + (threadIdx.x >> 5);
    int lane = threadIdx.x & 31;
    float* mrow = MSG + (size_t)tok * CDIM;

    if (mask[tok] == 0) {
        #pragma unroll
        for (int h = 0; h < HEADS; h++) mrow[h * 32 + lane] = 0.f;
        return;
    }
    int b = tok / LTOK;
    int c = cls[tok];
    const float* kvb = KV + (((size_t)b * NPROT + c) * HEADS) * (DHEAD * DHEAD);
    const float* ksb = KS + (((size_t)b * NPROT + c) * HEADS) * DHEAD;
    const float* qrow = Q + (size_t)tok * CDIM;

    #pragma unroll
    for (int h = 0; h < HEADS; h++) {
        float qd = qrow[h * 32 + lane];
        float den = warp_sum(qd * ksb[h * 32 + lane]) + EPS_ATTN;
        const float* kvh = kvb + h * (DHEAD * DHEAD);
        float num = 0.f;
        #pragma unroll
        for (int dd = 0; dd < 32; dd++)
            num += __shfl_sync(0xffffffffu, qd, dd) * kvh[dd * 32 + lane];
        mrow[h * 32 + lane] = num / den;
    }
}

// ---------------------------------------------------------------------------
// LayerNorm over last dim (256); warp per token
// ---------------------------------------------------------------------------
__global__ __launch_bounds__(256)
void ln_kernel(const float* __restrict__ X, const float* __restrict__ g,
               const float* __restrict__ b, float* __restrict__ Y)
{
    int tok = blockIdx.x * 8 + (threadIdx.x >> 5);
    int lane = threadIdx.x & 31;
    const float* x = X + (size_t)tok * CDIM;
    float v[8], s = 0.f;
    #pragma unroll
    for (int i = 0; i < 8; i++) { v[i] = x[i * 32 + lane]; s += v[i]; }
    float mean = warp_sum(s) * (1.f / 256.f);
    float s2 = 0.f;
    #pragma unroll
    for (int i = 0; i < 8; i++) { float dd = v[i] - mean; s2 += dd * dd; }
    float rs = rsqrtf(warp_sum(s2) * (1.f / 256.f) + EPS_LN);
    float* y = Y + (size_t)tok * CDIM;
    #pragma unroll
    for (int i = 0; i < 8; i++) {
        int cc = i * 32 + lane;
        y[cc] = (v[i] - mean) * rs * g[cc] + b[cc];
    }
}

// ---------------------------------------------------------------------------
// Final: x += LN(z)*g2+b2 at valid tokens only (in place)
// ---------------------------------------------------------------------------
__global__ __launch_bounds__(256)
void final_kernel(const float* __restrict__ Z, const float* __restrict__ g,
                  const float* __restrict__ b, const int* __restrict__ mask,
                  float* __restrict__ X)
{
    int tok = blockIdx.x * 8 + (threadIdx.x >> 5);
    int lane = threadIdx.x & 31;
    if (mask[tok] == 0) return;
    const float* z = Z + (size_t)tok * CDIM;
    float v[8], s = 0.f;
    #pragma unroll
    for (int i = 0; i < 8; i++) { v[i] = z[i * 32 + lane]; s += v[i]; }
    float mean = warp_sum(s) * (1.f / 256.f);
    float s2 = 0.f;
    #pragma unroll
    for (int i = 0; i < 8; i++) { float dd = v[i] - mean; s2 += dd * dd; }
    float rs = rsqrtf(warp_sum(s2) * (1.f / 256.f) + EPS_LN);
    float* x = X + (size_t)tok * CDIM;
    #pragma unroll
    for (int i = 0; i < 8; i++) {
        int cc = i * 32 + lane;
        x[cc] += (v[i] - mean) * rs * g[cc] + b[cc];
    }
}

// ---------------------------------------------------------------------------
// Copy
// ---------------------------------------------------------------------------
__global__ void copy_kernel(const float* __restrict__ s, float* __restrict__ d, int n)
{
    int i = blockIdx.x * blockDim.x + threadIdx.x;
    int stride = gridDim.x * blockDim.x;
    for (; i < n; i += stride) d[i] = s[i];
}

// ---------------------------------------------------------------------------
// Host orchestration
// ---------------------------------------------------------------------------
static void run_layer(float* x, const float* src,
                      const int* clsx, const int* clssrc,
                      const int* maskx, const int* masksrc,
                      const float* wq, const float* wk, const float* wv,
                      const float* wm, const float* w1, const float* w2,
                      const float* gg1, const float* bb1,
                      const float* gg2, const float* bb2,
                      float* q, float* k, float* v, float* msg, float* hid,
                      float* kv, float* ks)
{
    dim3 blk(256);
    dim3 g256(CDIM / BN, NTOK / BM);       // (2, 300)
    dim3 g512(2 * CDIM / BN, NTOK / BM);   // (4, 300)

    gemm_kernel<1, false><<<g256, blk>>>(x,   nullptr, CDIM, wq, CDIM, CDIM, q);
    gemm_kernel<1, false><<<g256, blk>>>(src, nullptr, CDIM, wk, CDIM, CDIM, k);
    gemm_kernel<0, false><<<g256, blk>>>(src, nullptr, CDIM, wv, CDIM, CDIM, v);

    stats_kernel<<<BATCH * NPROT * HEADS, blk>>>(k, v, clssrc, masksrc, kv, ks);
    apply_kernel<<<NTOK / 8, blk>>>(q, kv, ks, clsx, maskx, msg);

    gemm_kernel<0, false><<<g256, blk>>>(msg, nullptr, CDIM, wm, CDIM, CDIM, k);   // k := msg@Wm
    ln_kernel<<<NTOK / 8, blk>>>(k, gg1, bb1, msg);                                // msg := LN(...)

    gemm_kernel<2, true ><<<g512, blk>>>(x, msg, CDIM, w1, 2 * CDIM, 2 * CDIM, hid); // relu([x|msg]@W1)
    gemm_kernel<0, false><<<g256, blk>>>(hid, nullptr, 2 * CDIM, w2, CDIM, 2 * CDIM, q); // q := hid@W2
    final_kernel<<<NTOK / 8, blk>>>(q, gg2, bb2, maskx, x);
}

extern "C" void kernel_launch(void* const* d_in, const int* in_sizes, int n_in,
                              void* d_out, int out_size)
{
    const float* feat0 = (const float*)d_in[0];
    const float* feat1 = (const float*)d_in[1];
    const int*   mask0 = (const int*)  d_in[2];
    const int*   mask1 = (const int*)  d_in[3];
    const float* f0wp  = (const float*)d_in[4];
    const float* f1wp  = (const float*)d_in[5];
    const float* proto = (const float*)d_in[6];
    const float* Wq    = (const float*)d_in[7];
    const float* Wk    = (const float*)d_in[8];
    const float* Wv    = (const float*)d_in[9];
    const float* Wm    = (const float*)d_in[10];
    const float* W1    = (const float*)d_in[11];
    const float* W2    = (const float*)d_in[12];
    const float* G1    = (const float*)d_in[13];
    const float* B1    = (const float*)d_in[14];
    const float* G2    = (const float*)d_in[15];
    const float* B2    = (const float*)d_in[16];

    float* out = (float*)d_out;
    float* x0     = out + OF_F0;
    float* x1     = out + OF_F1;
    float* cls0f  = out + OF_C0;
    float* cls1f  = out + OF_C1;
    float* f0p    = out + OF_F0P;
    float* f1p    = out + OF_F1P;
    float* protoO = out + OF_PROT;

    float *q, *k, *v, *msg, *hid, *kv, *ks;
    int *c0, *c1;
    cudaGetSymbolAddress((void**)&q,   g_q);
    cudaGetSymbolAddress((void**)&k,   g_k);
    cudaGetSymbolAddress((void**)&v,   g_v);
    cudaGetSymbolAddress((void**)&msg, g_msg);
    cudaGetSymbolAddress((void**)&hid, g_hid);
    cudaGetSymbolAddress((void**)&kv,  g_kv);
    cudaGetSymbolAddress((void**)&ks,  g_ks);
    cudaGetSymbolAddress((void**)&c0,  g_cls0);
    cudaGetSymbolAddress((void**)&c1,  g_cls1);

    // Init: working features live directly in the output buffer.
    copy_kernel<<<2048, 256>>>(feat0, x0, NTOK * CDIM);
    copy_kernel<<<2048, 256>>>(feat1, x1, NTOK * CDIM);
    copy_kernel<<<8, 256>>>(proto, protoO, NPROT * CDIM);

    classify_kernel<<<NTOK / 8, 256>>>(f0wp, proto, f0p, cls0f, c0);
    classify_kernel<<<NTOK / 8, 256>>>(f1wp, proto, f1p, cls1f, c1);

    for (int i = 0; i < NLAYER; i++) {
        const float* wq = Wq + (size_t)i * CDIM * CDIM;
        const float* wk = Wk + (size_t)i * CDIM * CDIM;
        const float* wv = Wv + (size_t)i * CDIM * CDIM;
        const float* wm = Wm + (size_t)i * CDIM * CDIM;
        const float* w1 = W1 + (size_t)i * 2 * CDIM * 2 * CDIM;
        const float* w2 = W2 + (size_t)i * 2 * CDIM * CDIM;
        const float* gg1 = G1 + (size_t)i * CDIM;
        const float* bb1 = B1 + (size_t)i * CDIM;
        const float* gg2 = G2 + (size_t)i * CDIM;
        const float* bb2 = B2 + (size_t)i * CDIM;

        if ((i & 1) == 0) {  // self-self
            run_layer(x0, x0, c0, c0, mask0, mask0,
                      wq, wk, wv, wm, w1, w2, gg1, bb1, gg2, bb2,
                      q, k, v, msg, hid, kv, ks);
            run_layer(x1, x1, c1, c1, mask1, mask1,
                      wq, wk, wv, wm, w1, w2, gg1, bb1, gg2, bb2,
                      q, k, v, msg, hid, kv, ks);
        } else {             // cross-self: feat0 attends feat1, then feat1 attends UPDATED feat0
            run_layer(x0, x1, c0, c1, mask0, mask1,
                      wq, wk, wv, wm, w1, w2, gg1, bb1, gg2, bb2,
                      q, k, v, msg, hid, kv, ks);
            run_layer(x1, x0, c1, c0, mask1, mask0,
                      wq, wk, wv, wm, w1, w2, gg1, bb1, gg2, bb2,
                      q, k, v, msg, hid, kv, ks);
        }
    }
    (void)in_sizes; (void)n_in; (void)out_size;
}

// round 3
// speedup vs baseline: 2.2231x; 2.2231x over previous
#include <cuda_runtime.h>
#include <cuda_bf16.h>
#include <math.h>
#include <stdint.h>

// ---------------------------------------------------------------------------
// Problem constants
// ---------------------------------------------------------------------------
#define BATCH 8
#define LTOK  4800
#define CDIM  256
#define HEADS 8
#define DHEAD 32
#define NPROT 8
#define NLAYER 4
#define NTOK  (BATCH * LTOK)          // 38400
#define EPS_ATTN 1e-6f
#define EPS_LN   1e-5f

// Output layout (floats), tuple order:
// feat0, feat1, class0, class1, f0p, f1p, prototype
#define OF_F0    0
#define OF_F1    (NTOK * CDIM)
#define OF_C0    (2 * NTOK * CDIM)
#define OF_C1    (OF_C0 + NTOK)
#define OF_F0P   (OF_C1 + NTOK)
#define OF_F1P   (OF_F0P + NTOK * NPROT)
#define OF_PROT  (OF_F1P + NTOK * NPROT)

// ---------------------------------------------------------------------------
// Device scratch (no allocation allowed)
// ---------------------------------------------------------------------------
__device__ __align__(16) float g_q  [NTOK * CDIM];
__device__ __align__(16) float g_k  [NTOK * CDIM];
__device__ __align__(16) float g_v  [NTOK * CDIM];
__device__ __align__(16) float g_msg[NTOK * CDIM];
__device__ __align__(16) float g_hid[NTOK * 2 * CDIM];
__device__ __align__(16) float g_kv [BATCH * NPROT * HEADS * DHEAD * DHEAD];
__device__ __align__(16) float g_ks [BATCH * NPROT * HEADS * DHEAD];
__device__ int   g_cls0[NTOK];
__device__ int   g_cls1[NTOK];
__device__ int   g_list0[BATCH * NPROT * LTOK];
__device__ int   g_list1[BATCH * NPROT * LTOK];
__device__ int   g_cnt0[BATCH * NPROT];
__device__ int   g_cnt1[BATCH * NPROT];

// Transposed+split weights per layer: Wq',Wk',Wv',Wm' (65536 each),
// W1' (262144), W2' (131072) => 655360 bf16 per layer
#define WOFF_Q 0
#define WOFF_K 65536
#define WOFF_V 131072
#define WOFF_M 196608
#define WOFF_1 262144
#define WOFF_2 524288
#define WLSZ   655360
__device__ __align__(16) __nv_bfloat16 g_whi[NLAYER * WLSZ];
__device__ __align__(16) __nv_bfloat16 g_wlo[NLAYER * WLSZ];

// ---------------------------------------------------------------------------
// Helpers
// ---------------------------------------------------------------------------
__device__ __forceinline__ uint32_t smem_u32(const void* p) {
    uint32_t a;
    asm("{ .reg .u64 t; cvta.to.shared.u64 t, %1; cvt.u32.u64 %0, t; }"
        : "=r"(a) : "l"(p));
    return a;
}
__device__ __forceinline__ float warp_sum(float v) {
    #pragma unroll
    for (int o = 16; o; o >>= 1) v += __shfl_xor_sync(0xffffffffu, v, o);
    return v;
}
__device__ __forceinline__ void ldsm4(uint32_t* r, uint32_t addr) {
    asm volatile("ldmatrix.sync.aligned.m8n8.x4.shared.b16 {%0,%1,%2,%3}, [%4];"
                 : "=r"(r[0]), "=r"(r[1]), "=r"(r[2]), "=r"(r[3]) : "r"(addr));
}
__device__ __forceinline__ void mma16816(float* c, const uint32_t* a,
                                         uint32_t b0, uint32_t b1) {
    asm volatile(
        "mma.sync.aligned.m16n8k16.row.col.f32.bf16.bf16.f32 "
        "{%0,%1,%2,%3}, {%4,%5,%6,%7}, {%8,%9}, {%0,%1,%2,%3};"
        : "+f"(c[0]), "+f"(c[1]), "+f"(c[2]), "+f"(c[3])
        : "r"(a[0]), "r"(a[1]), "r"(a[2]), "r"(a[3]), "r"(b0), "r"(b1));
}
__device__ __forceinline__ void cpasync16(uint32_t dst, const __nv_bfloat16* src) {
    asm volatile("cp.async.cg.shared.global [%0], [%1], 16;"
                 :: "r"(dst), "l"(__cvta_generic_to_global(src)));
}
#define CP_COMMIT() asm volatile("cp.async.commit_group;" ::: "memory")

// ---------------------------------------------------------------------------
// mma.sync GEMM: C[M,N] = f(A_fp32[M,K] @ W[K,N]) with bf16 hi/lo 3-pass.
// Bhi/Blo = W transposed to [N,K] (K-contiguous) -> mma row.col directly.
// CTA tile 128x128, K-chunks of 32, 2-stage cp.async pipeline.
// EPI: 0 none, 1 phi=elu+1, 2 relu.  CONCAT: A is k<256, A2 is k>=256.
// ---------------------------------------------------------------------------
#define RS      40                     // SMEM row stride (bf16) -> 80B, conflict-free
#define TILE_B  (128 * RS * 2)         // 10240 B per matrix tile
#define SA_HI   0
#define SA_LO   10240
#define SB_HI   20480
#define SB_LO   30720
#define STG_SZ  40960
#define DYN_SMEM (2 * STG_SZ)          // 81920

template <int EPI, bool CONCAT>
__global__ __launch_bounds__(256, 2)
void gemm_mma(const float* __restrict__ A, const float* __restrict__ A2, int lda,
              const __nv_bfloat16* __restrict__ Bhi,
              const __nv_bfloat16* __restrict__ Blo,
              int K, float* __restrict__ C, int cstride)
{
    extern __shared__ __align__(128) char sm[];
    const uint32_t sbase = smem_u32(sm);
    const int tid  = threadIdx.x;
    const int lane = tid & 31;
    const int wid  = tid >> 5;
    const int wm   = wid >> 1;         // 0..3 -> M offset wm*32
    const int wn   = wid & 1;          // 0..1 -> N offset wn*64
    const int m0   = blockIdx.y * 128;
    const int n0   = blockIdx.x * 128;
    const int chunks = K >> 5;

    float acc[2][8][4];
    #pragma unroll
    for (int i = 0; i < 2; i++)
        #pragma unroll
        for (int j = 0; j < 8; j++)
            #pragma unroll
            for (int t = 0; t < 4; t++) acc[i][j][t] = 0.f;

    auto issue = [&](int c) {
        const int buf = c & 1;
        const uint32_t stg = sbase + buf * STG_SZ;
        const int k0 = c * 32;
        const float* Asrc = A;
        int koff = k0;
        if (CONCAT && k0 >= 256) { Asrc = A2; koff = k0 - 256; }
        // A: 128 rows x 32 k fp32 -> bf16 hi/lo (1024 float4 slots)
        #pragma unroll
        for (int i = 0; i < 4; i++) {
            int idx = tid + i * 256;
            int row = idx >> 3;
            int seg = idx & 7;
            float4 f = *(const float4*)(Asrc + (size_t)(m0 + row) * lda + koff + seg * 4);
            __nv_bfloat162 h0, h1, l0, l1;
            h0.x = __float2bfloat16(f.x); h0.y = __float2bfloat16(f.y);
            h1.x = __float2bfloat16(f.z); h1.y = __float2bfloat16(f.w);
            l0.x = __float2bfloat16(f.x - __bfloat162float(h0.x));
            l0.y = __float2bfloat16(f.y - __bfloat162float(h0.y));
            l1.x = __float2bfloat16(f.z - __bfloat162float(h1.x));
            l1.y = __float2bfloat16(f.w - __bfloat162float(h1.y));
            uint32_t off = (uint32_t)(row * RS + seg * 4) * 2;
            *(uint2*)(sm + buf * STG_SZ + SA_HI + off) =
                make_uint2(*(uint32_t*)&h0, *(uint32_t*)&h1);
            *(uint2*)(sm + buf * STG_SZ + SA_LO + off) =
                make_uint2(*(uint32_t*)&l0, *(uint32_t*)&l1);
        }
        // B: 128 n-rows x 32 k bf16 via cp.async (512 slots of 16B, hi+lo)
        #pragma unroll
        for (int i = 0; i < 2; i++) {
            int idx = tid + i * 256;
            int row = idx >> 2;
            int seg = idx & 3;
            uint32_t doff = (uint32_t)(row * RS + seg * 8) * 2;
            size_t goff = (size_t)(n0 + row) * K + k0 + seg * 8;
            cpasync16(stg + SB_HI + doff, Bhi + goff);
            cpasync16(stg + SB_LO + doff, Blo + goff);
        }
    };

    issue(0); CP_COMMIT();

    for (int c = 0; c < chunks; c++) {
        const bool more = (c + 1 < chunks);
        if (more) { issue(c + 1); CP_COMMIT(); }
        if (more) asm volatile("cp.async.wait_group 1;" ::: "memory");
        else      asm volatile("cp.async.wait_group 0;" ::: "memory");
        __syncthreads();

        const uint32_t stg = sbase + (c & 1) * STG_SZ;
        // lane address components (ldmatrix x4)
        const int arow = wm * 32 + (lane & 15);
        const int ako  = (lane >> 4) << 3;
        const int brow = wn * 64 + ((lane >> 4) << 3) + (lane & 7);
        const int bko  = ((lane >> 3) & 1) << 3;

        #pragma unroll
        for (int ks = 0; ks < 2; ks++) {
            const int ko = ks * 16;
            uint32_t ah[2][4], al[2][4], bf[4][4];
            #pragma unroll
            for (int mt = 0; mt < 2; mt++) {
                uint32_t ad = stg + SA_HI + (uint32_t)((arow + mt * 16) * RS + ko + ako) * 2;
                ldsm4(ah[mt], ad);
                ldsm4(al[mt], ad + (SA_LO - SA_HI));
            }
            #pragma unroll
            for (int g = 0; g < 4; g++) {
                uint32_t bd = stg + SB_HI + (uint32_t)((brow + g * 16) * RS + ko + bko) * 2;
                ldsm4(bf[g], bd);
            }
            // pass 1: Ahi*Bhi  +  pass 3: Alo*Bhi
            #pragma unroll
            for (int mt = 0; mt < 2; mt++)
                #pragma unroll
                for (int g = 0; g < 4; g++) {
                    mma16816(acc[mt][g * 2 + 0], ah[mt], bf[g][0], bf[g][1]);
                    mma16816(acc[mt][g * 2 + 1], ah[mt], bf[g][2], bf[g][3]);
                    mma16816(acc[mt][g * 2 + 0], al[mt], bf[g][0], bf[g][1]);
                    mma16816(acc[mt][g * 2 + 1], al[mt], bf[g][2], bf[g][3]);
                }
            // pass 2: Ahi*Blo (reuse bf regs)
            #pragma unroll
            for (int g = 0; g < 4; g++) {
                uint32_t bd = stg + SB_LO + (uint32_t)((brow + g * 16) * RS + ko + bko) * 2;
                ldsm4(bf[g], bd);
            }
            #pragma unroll
            for (int mt = 0; mt < 2; mt++)
                #pragma unroll
                for (int g = 0; g < 4; g++) {
                    mma16816(acc[mt][g * 2 + 0], ah[mt], bf[g][0], bf[g][1]);
                    mma16816(acc[mt][g * 2 + 1], ah[mt], bf[g][2], bf[g][3]);
                }
        }
        __syncthreads();
    }

    // Epilogue: fragment -> gmem (float2 pairs)
    const int gp = lane >> 2;
    const int tq = lane & 3;
    #pragma unroll
    for (int mt = 0; mt < 2; mt++) {
        #pragma unroll
        for (int nt = 0; nt < 8; nt++) {
            float* cc = acc[mt][nt];
            #pragma unroll
            for (int t = 0; t < 4; t++) {
                float v = cc[t];
                if (EPI == 1) v = (v > 0.f) ? (v + 1.f) : expf(v);
                else if (EPI == 2) v = fmaxf(v, 0.f);
                cc[t] = v;
            }
            size_t row = (size_t)(m0 + wm * 32 + mt * 16 + gp);
            int col = n0 + wn * 64 + nt * 8 + tq * 2;
            *(float2*)(C + row * cstride + col)       = make_float2(cc[0], cc[1]);
            *(float2*)(C + (row + 8) * cstride + col) = make_float2(cc[2], cc[3]);
        }
    }
}

// ---------------------------------------------------------------------------
// Weight prep: out[n*K + k] = split(W[k*N + n]) into bf16 hi/lo
// ---------------------------------------------------------------------------
__global__ void prep_w(const float* __restrict__ W, int Kd, int Nd,
                       __nv_bfloat16* __restrict__ hi, __nv_bfloat16* __restrict__ lo)
{
    int idx = blockIdx.x * blockDim.x + threadIdx.x;
    if (idx >= Kd * Nd) return;
    int n = idx / Kd;
    int k = idx - n * Kd;
    float w = W[(size_t)k * Nd + n];
    __nv_bfloat16 h = __float2bfloat16(w);
    hi[idx] = h;
    lo[idx] = __float2bfloat16(w - __bfloat162float(h));
}

// ---------------------------------------------------------------------------
// Classification: fp = feat_wo_pe @ proto^T, argmax -> class (warp/token)
// ---------------------------------------------------------------------------
__global__ __launch_bounds__(256)
void classify_kernel(const float* __restrict__ fwp, const float* __restrict__ proto,
                     float* __restrict__ out_fp, float* __restrict__ out_clsf,
                     int* __restrict__ cls)
{
    __shared__ float sp[NPROT][CDIM];
    int tid = threadIdx.x;
    #pragma unroll
    for (int i = 0; i < 8; i++) {
        int idx = tid + i * 256;
        sp[idx >> 8][idx & 255] = proto[idx];
    }
    __syncthreads();

    int tok = blockIdx.x * 8 + (tid >> 5);
    int lane = tid & 31;
    const float* f = fwp + (size_t)tok * CDIM;

    float acc[NPROT];
    #pragma unroll
    for (int p = 0; p < NPROT; p++) acc[p] = 0.f;
    #pragma unroll
    for (int i = 0; i < 8; i++) {
        float x = f[lane + i * 32];
        #pragma unroll
        for (int p = 0; p < NPROT; p++) acc[p] += x * sp[p][lane + i * 32];
    }
    #pragma unroll
    for (int p = 0; p < NPROT; p++) acc[p] = warp_sum(acc[p]);

    if (lane < NPROT) out_fp[(size_t)tok * NPROT + lane] = acc[lane];
    if (lane == 0) {
        int best = 0; float bv = acc[0];
        #pragma unroll
        for (int p = 1; p < NPROT; p++) if (acc[p] > bv) { bv = acc[p]; best = p; }
        cls[tok] = best;
        out_clsf[tok] = (float)best;
    }
}

// ---------------------------------------------------------------------------
// Token list build: per (b,c), deterministic ballot compaction. 32 thr/block.
// ---------------------------------------------------------------------------
__global__ void build_list(const int* __restrict__ cls, const int* __restrict__ mask,
                           int* __restrict__ list, int* __restrict__ cnt)
{
    int g = blockIdx.x;              // b*8 + c
    int b = g >> 3, c = g & 7;
    int lane = threadIdx.x;
    const int* cb = cls + b * LTOK;
    const int* mb = mask + b * LTOK;
    int base = g * LTOK;
    int count = 0;
    for (int s0 = 0; s0 < LTOK; s0 += 32) {
        int s = s0 + lane;
        bool hit = (cb[s] == c) && (mb[s] != 0);
        unsigned m = __ballot_sync(0xffffffffu, hit);
        if (hit) list[base + count + __popc(m & ((1u << lane) - 1u))] = s;
        count += __popc(m);
    }
    if (lane == 0) cnt[g] = count;
}

// ---------------------------------------------------------------------------
// Per-class linear-attention stats via token lists. Block per (b,c,h).
// ---------------------------------------------------------------------------
__global__ __launch_bounds__(256)
void stats_kernel(const float* __restrict__ K_, const float* __restrict__ V_,
                  const int* __restrict__ list, const int* __restrict__ cnt,
                  float* __restrict__ KV, float* __restrict__ KS)
{
    __shared__ float sk[32][33];
    __shared__ float sv[32][33];
    __shared__ int   st[32];

    int bid = blockIdx.x;            // b*64 + c*8 + h
    int h = bid & 7;
    int c = (bid >> 3) & 7;
    int b = bid >> 6;
    int g = b * 8 + c;

    int tid = threadIdx.x;
    int d  = tid >> 3;
    int e0 = (tid & 7) * 4;

    float a0 = 0.f, a1 = 0.f, a2 = 0.f, a3 = 0.f;
    float ssum = 0.f;

    const float* Kb = K_ + (size_t)b * LTOK * CDIM + h * DHEAD;
    const float* Vb = V_ + (size_t)b * LTOK * CDIM + h * DHEAD;
    int n = cnt[g];
    int base = g * LTOK;

    for (int i0 = 0; i0 < n; i0 += 32) {
        if (tid < 32) st[tid] = (i0 + tid < n) ? list[base + i0 + tid] : -1;
        __syncthreads();
        #pragma unroll
        for (int i = 0; i < 4; i++) {
            int idx = tid + i * 256;
            int s = idx >> 5;
            int dd = idx & 31;
            int t = st[s];
            float kk = 0.f, vv = 0.f;
            if (t >= 0) {
                kk = Kb[(size_t)t * CDIM + dd];
                vv = Vb[(size_t)t * CDIM + dd];
            }
            sk[s][dd] = kk;
            sv[s][dd] = vv;
        }
        __syncthreads();
        #pragma unroll
        for (int s = 0; s < 32; s++) {
            float kd = sk[s][d];
            a0 += kd * sv[s][e0 + 0];
            a1 += kd * sv[s][e0 + 1];
            a2 += kd * sv[s][e0 + 2];
            a3 += kd * sv[s][e0 + 3];
        }
        if (tid < 32) {
            #pragma unroll
            for (int s = 0; s < 32; s++) ssum += sk[s][tid];
        }
        __syncthreads();
    }

    size_t o = ((((size_t)b * NPROT + c) * HEADS + h) * DHEAD + d) * DHEAD + e0;
    KV[o + 0] = a0; KV[o + 1] = a1; KV[o + 2] = a2; KV[o + 3] = a3;
    if (tid < 32) KS[(((size_t)b * NPROT + c) * HEADS + h) * DHEAD + tid] = ssum;
}

// ---------------------------------------------------------------------------
// Apply: block per (b,c); kv/ks staged in SMEM; warp per token from list.
// ---------------------------------------------------------------------------
__global__ __launch_bounds__(256)
void apply_kernel(const float* __restrict__ Q, const float* __restrict__ KV,
                  const float* __restrict__ KS, const int* __restrict__ list,
                  const int* __restrict__ cnt, float* __restrict__ MSG)
{
    __shared__ float skv[HEADS][DHEAD][DHEAD];   // 32 KB
    __shared__ float sks[HEADS][DHEAD];

    int g = blockIdx.x;              // b*8 + c
    int b = g >> 3;
    int tid = threadIdx.x;
    int w = tid >> 5, lane = tid & 31;

    for (int i = tid; i < HEADS * DHEAD * DHEAD; i += 256)
        skv[i >> 10][(i >> 5) & 31][i & 31] = KV[(size_t)g * HEADS * DHEAD * DHEAD + i];
    for (int i = tid; i < HEADS * DHEAD; i += 256)
        sks[i >> 5][i & 31] = KS[(size_t)g * HEADS * DHEAD + i];
    __syncthreads();

    int n = cnt[g];
    int base = g * LTOK;

    for (int i0 = 0; i0 < n; i0 += 8) {
        int ii = i0 + w;
        if (ii < n) {
            int t = list[base + ii];
            const float* qrow = Q + ((size_t)b * LTOK + t) * CDIM;
            float* mrow = MSG + ((size_t)b * LTOK + t) * CDIM;
            #pragma unroll
            for (int h = 0; h < HEADS; h++) {
                float qd = qrow[h * 32 + lane];
                float den = warp_sum(qd * sks[h][lane]) + EPS_ATTN;
                float num = 0.f;
                #pragma unroll
                for (int dd = 0; dd < 32; dd++)
                    num += __shfl_sync(0xffffffffu, qd, dd) * skv[h][dd][lane];
                mrow[h * 32 + lane] = num / den;
            }
        }
    }
}

// ---------------------------------------------------------------------------
// LayerNorm (warp/token)
// ---------------------------------------------------------------------------
__global__ __launch_bounds__(256)
void ln_kernel(const float* __restrict__ X, const float* __restrict__ g,
               const float* __restrict__ b, float* __restrict__ Y)
{
    int tok = blockIdx.x * 8 + (threadIdx.x >> 5);
    int lane = threadIdx.x & 31;
    const float* x = X + (size_t)tok * CDIM;
    float v[8], s = 0.f;
    #pragma unroll
    for (int i = 0; i < 8; i++) { v[i] = x[i * 32 + lane]; s += v[i]; }
    float mean = warp_sum(s) * (1.f / 256.f);
    float s2 = 0.f;
    #pragma unroll
    for (int i = 0; i < 8; i++) { float dd = v[i] - mean; s2 += dd * dd; }
    float rs = rsqrtf(warp_sum(s2) * (1.f / 256.f) + EPS_LN);
    float* y = Y + (size_t)tok * CDIM;
    #pragma unroll
    for (int i = 0; i < 8; i++) {
        int cc = i * 32 + lane;
        y[cc] = (v[i] - mean) * rs * g[cc] + b[cc];
    }
}

// ---------------------------------------------------------------------------
// Final: x += LN(z)*g2+b2 at valid tokens (in place)
// ---------------------------------------------------------------------------
__global__ __launch_bounds__(256)
void final_kernel(const float* __restrict__ Z, const float* __restrict__ g,
                  const float* __restrict__ b, const int* __restrict__ mask,
                  float* __restrict__ X)
{
    int tok = blockIdx.x * 8 + (threadIdx.x >> 5);
    int lane = threadIdx.x & 31;
    if (mask[tok] == 0) return;
    const float* z = Z + (size_t)tok * CDIM;
    float v[8], s = 0.f;
    #pragma unroll
    for (int i = 0; i < 8; i++) { v[i] = z[i * 32 + lane]; s += v[i]; }
    float mean = warp_sum(s) * (1.f / 256.f);
    float s2 = 0.f;
    #pragma unroll
    for (int i = 0; i < 8; i++) { float dd = v[i] - mean; s2 += dd * dd; }
    float rs = rsqrtf(warp_sum(s2) * (1.f / 256.f) + EPS_LN);
    float* x = X + (size_t)tok * CDIM;
    #pragma unroll
    for (int i = 0; i < 8; i++) {
        int cc = i * 32 + lane;
        x[cc] += (v[i] - mean) * rs * g[cc] + b[cc];
    }
}

__global__ void copy_kernel(const float* __restrict__ s, float* __restrict__ d, int n)
{
    int i = blockIdx.x * blockDim.x + threadIdx.x;
    int stride = gridDim.x * blockDim.x;
    for (; i < n; i += stride) d[i] = s[i];
}

// ---------------------------------------------------------------------------
// Host orchestration
// ---------------------------------------------------------------------------
static void run_layer(float* x, const float* src,
                      const int* listx, const int* cntx,
                      const int* listsrc, const int* cntsrc,
                      const int* maskx,
                      const __nv_bfloat16* whi, const __nv_bfloat16* wlo,
                      const float* gg1, const float* bb1,
                      const float* gg2, const float* bb2,
                      float* q, float* k, float* v, float* msg, float* hid,
                      float* kv, float* ks)
{
    dim3 blk(256);
    dim3 gN256(2, NTOK / 128);     // 2 x 300
    dim3 gN512(4, NTOK / 128);     // 4 x 300

    gemm_mma<1, false><<<gN256, blk, DYN_SMEM>>>(x,   nullptr, CDIM, whi + WOFF_Q, wlo + WOFF_Q, 256, q, CDIM);
    gemm_mma<1, false><<<gN256, blk, DYN_SMEM>>>(src, nullptr, CDIM, whi + WOFF_K, wlo + WOFF_K, 256, k, CDIM);
    gemm_mma<0, false><<<gN256, blk, DYN_SMEM>>>(src, nullptr, CDIM, whi + WOFF_V, wlo + WOFF_V, 256, v, CDIM);

    stats_kernel<<<BATCH * NPROT * HEADS, blk>>>(k, v, listsrc, cntsrc, kv, ks);
    apply_kernel<<<BATCH * NPROT, blk>>>(q, kv, ks, listx, cntx, msg);

    gemm_mma<0, false><<<gN256, blk, DYN_SMEM>>>(msg, nullptr, CDIM, whi + WOFF_M, wlo + WOFF_M, 256, k, CDIM);
    ln_kernel<<<NTOK / 8, blk>>>(k, gg1, bb1, msg);

    gemm_mma<2, true ><<<gN512, blk, DYN_SMEM>>>(x, msg, CDIM, whi + WOFF_1, wlo + WOFF_1, 512, hid, 2 * CDIM);
    gemm_mma<0, false><<<gN256, blk, DYN_SMEM>>>(hid, nullptr, 2 * CDIM, whi + WOFF_2, wlo + WOFF_2, 512, q, CDIM);
    final_kernel<<<NTOK / 8, blk>>>(q, gg2, bb2, maskx, x);
}

extern "C" void kernel_launch(void* const* d_in, const int* in_sizes, int n_in,
                              void* d_out, int out_size)
{
    const float* feat0 = (const float*)d_in[0];
    const float* feat1 = (const float*)d_in[1];
    const int*   mask0 = (const int*)  d_in[2];
    const int*   mask1 = (const int*)  d_in[3];
    const float* f0wp  = (const float*)d_in[4];
    const float* f1wp  = (const float*)d_in[5];
    const float* proto = (const float*)d_in[6];
    const float* Wq    = (const float*)d_in[7];
    const float* Wk    = (const float*)d_in[8];
    const float* Wv    = (const float*)d_in[9];
    const float* Wm    = (const float*)d_in[10];
    const float* W1    = (const float*)d_in[11];
    const float* W2    = (const float*)d_in[12];
    const float* G1    = (const float*)d_in[13];
    const float* B1    = (const float*)d_in[14];
    const float* G2    = (const float*)d_in[15];
    const float* B2    = (const float*)d_in[16];

    cudaFuncSetAttribute(gemm_mma<0, false>, cudaFuncAttributeMaxDynamicSharedMemorySize, DYN_SMEM);
    cudaFuncSetAttribute(gemm_mma<1, false>, cudaFuncAttributeMaxDynamicSharedMemorySize, DYN_SMEM);
    cudaFuncSetAttribute(gemm_mma<2, true >, cudaFuncAttributeMaxDynamicSharedMemorySize, DYN_SMEM);

    float* out = (float*)d_out;
    float* x0     = out + OF_F0;
    float* x1     = out + OF_F1;
    float* cls0f  = out + OF_C0;
    float* cls1f  = out + OF_C1;
    float* f0p    = out + OF_F0P;
    float* f1p    = out + OF_F1P;
    float* protoO = out + OF_PROT;

    float *q, *k, *v, *msg, *hid, *kv, *ks;
    int *c0, *c1, *l0, *l1, *n0, *n1;
    __nv_bfloat16 *whi, *wlo;
    cudaGetSymbolAddress((void**)&q,   g_q);
    cudaGetSymbolAddress((void**)&k,   g_k);
    cudaGetSymbolAddress((void**)&v,   g_v);
    cudaGetSymbolAddress((void**)&msg, g_msg);
    cudaGetSymbolAddress((void**)&hid, g_hid);
    cudaGetSymbolAddress((void**)&kv,  g_kv);
    cudaGetSymbolAddress((void**)&ks,  g_ks);
    cudaGetSymbolAddress((void**)&c0,  g_cls0);
    cudaGetSymbolAddress((void**)&c1,  g_cls1);
    cudaGetSymbolAddress((void**)&l0,  g_list0);
    cudaGetSymbolAddress((void**)&l1,  g_list1);
    cudaGetSymbolAddress((void**)&n0,  g_cnt0);
    cudaGetSymbolAddress((void**)&n1,  g_cnt1);
    cudaGetSymbolAddress((void**)&whi, g_whi);
    cudaGetSymbolAddress((void**)&wlo, g_wlo);

    // Init outputs: working features live directly in the output buffer.
    copy_kernel<<<2048, 256>>>(feat0, x0, NTOK * CDIM);
    copy_kernel<<<2048, 256>>>(feat1, x1, NTOK * CDIM);
    copy_kernel<<<8, 256>>>(proto, protoO, NPROT * CDIM);

    classify_kernel<<<NTOK / 8, 256>>>(f0wp, proto, f0p, cls0f, c0);
    classify_kernel<<<NTOK / 8, 256>>>(f1wp, proto, f1p, cls1f, c1);
    build_list<<<BATCH * NPROT, 32>>>(c0, mask0, l0, n0);
    build_list<<<BATCH * NPROT, 32>>>(c1, mask1, l1, n1);

    // Weight prep: transpose + bf16 hi/lo split, all layers.
    for (int i = 0; i < NLAYER; i++) {
        __nv_bfloat16* hb = whi + (size_t)i * WLSZ;
        __nv_bfloat16* lb = wlo + (size_t)i * WLSZ;
        prep_w<<<(65536 + 255) / 256, 256>>>(Wq + (size_t)i * 65536, 256, 256, hb + WOFF_Q, lb + WOFF_Q);
        prep_w<<<(65536 + 255) / 256, 256>>>(Wk + (size_t)i * 65536, 256, 256, hb + WOFF_K, lb + WOFF_K);
        prep_w<<<(65536 + 255) / 256, 256>>>(Wv + (size_t)i * 65536, 256, 256, hb + WOFF_V, lb + WOFF_V);
        prep_w<<<(65536 + 255) / 256, 256>>>(Wm + (size_t)i * 65536, 256, 256, hb + WOFF_M, lb + WOFF_M);
        prep_w<<<(262144 + 255) / 256, 256>>>(W1 + (size_t)i * 262144, 512, 512, hb + WOFF_1, lb + WOFF_1);
        prep_w<<<(131072 + 255) / 256, 256>>>(W2 + (size_t)i * 131072, 512, 256, hb + WOFF_2, lb + WOFF_2);
    }

    for (int i = 0; i < NLAYER; i++) {
        const __nv_bfloat16* hb = whi + (size_t)i * WLSZ;
        const __nv_bfloat16* lb = wlo + (size_t)i * WLSZ;
        const float* gg1 = G1 + (size_t)i * CDIM;
        const float* bb1 = B1 + (size_t)i * CDIM;
        const float* gg2 = G2 + (size_t)i * CDIM;
        const float* bb2 = B2 + (size_t)i * CDIM;

        if ((i & 1) == 0) {  // self-self
            run_layer(x0, x0, l0, n0, l0, n0, mask0, hb, lb, gg1, bb1, gg2, bb2,
                      q, k, v, msg, hid, kv, ks);
            run_layer(x1, x1, l1, n1, l1, n1, mask1, hb, lb, gg1, bb1, gg2, bb2,
                      q, k, v, msg, hid, kv, ks);
        } else {             // cross-self
            run_layer(x0, x1, l0, n0, l1, n1, mask0, hb, lb, gg1, bb1, gg2, bb2,
                      q, k, v, msg, hid, kv, ks);
            run_layer(x1, x0, l1, n1, l0, n0, mask1, hb, lb, gg1, bb1, gg2, bb2,
                      q, k, v, msg, hid, kv, ks);
        }
    }
    (void)in_sizes; (void)n_in; (void)out_size;
}